// round 9
// baseline (speedup 1.0000x reference)
#include <cuda_runtime.h>
#include <cuda_fp16.h>
#include <cstdint>
#include <cstddef>

#define S_SRC 2048
#define S_TGT 2048
#define BATCH 16
#define HDIM  256
#define NCHUNK 4
#define NB     (BATCH / NCHUNK)

typedef __half f16;

// ---------------------------------------------------------------------------
// Device-global scratch (allocation-free rule)
// ---------------------------------------------------------------------------
__device__ f16   g_dec_hi [(size_t)BATCH * S_TGT * HDIM];   // [b][t][h]
__device__ f16   g_dec_lo [(size_t)BATCH * S_TGT * HDIM];
__device__ f16   g_enc_hi [(size_t)BATCH * S_SRC * HDIM];   // [b][s][h]
__device__ f16   g_enc_lo [(size_t)BATCH * S_SRC * HDIM];
__device__ f16   g_encT_hi[(size_t)BATCH * HDIM  * S_SRC];  // [b][h][s]
__device__ float g_S      [(size_t)BATCH * S_TGT * S_SRC];  // fp32 scores
__device__ f16   g_P_hi   [(size_t)BATCH * S_TGT * S_SRC];  // probs fp16

__device__ __forceinline__ uint32_t smem_u32(const void* p) {
    uint32_t a;
    asm("{ .reg .u64 t; cvta.to.shared.u64 t, %1; cvt.u32.u64 %0, t; }" : "=r"(a) : "l"(p));
    return a;
}
__device__ __forceinline__ void cp_async16(uint32_t dst, const void* src) {
    asm volatile("cp.async.cg.shared.global [%0], [%1], 16;" :: "r"(dst), "l"(src));
}
#define CP_COMMIT() asm volatile("cp.async.commit_group;")
#define CP_WAIT(N)  asm volatile("cp.async.wait_group %0;" :: "n"(N))

__device__ __forceinline__ void ldsm4(unsigned* r, uint32_t a) {
    asm volatile("ldmatrix.sync.aligned.m8n8.x4.shared.b16 {%0,%1,%2,%3}, [%4];"
                 : "=r"(r[0]), "=r"(r[1]), "=r"(r[2]), "=r"(r[3]) : "r"(a));
}
__device__ __forceinline__ void mma_f16(float* d, const unsigned* a, const unsigned* b) {
    asm volatile(
        "mma.sync.aligned.m16n8k16.row.col.f32.f16.f16.f32 "
        "{%0,%1,%2,%3}, {%4,%5,%6,%7}, {%8,%9}, {%0,%1,%2,%3};\n"
        : "+f"(d[0]), "+f"(d[1]), "+f"(d[2]), "+f"(d[3])
        : "r"(a[0]), "r"(a[1]), "r"(a[2]), "r"(a[3]), "r"(b[0]), "r"(b[1]));
}
__device__ __forceinline__ void split_f16(float v, f16& hi, f16& lo) {
    hi = __float2half_rn(v);
    lo = __float2half_rn(v - __half2float(hi));
}

// ---------------------------------------------------------------------------
// GEMM body (role QK: SPLIT=true, role PV: SPLIT=false)
// Block 128x128, K-chunk 32, double-buffered cp.async, 8 warps (2m x 4n).
// ---------------------------------------------------------------------------
#define ROWB   80
#define ARR    (128 * ROWB)
#define GSMEM3 (2 * 4 * ARR)   // 81920 (stage kernel always launches with this)

__device__ __forceinline__ void load_tile(uint32_t dst, const f16* __restrict__ g,
                                          int ldg, int tid) {
    #pragma unroll
    for (int it = tid; it < 512; it += 256) {
        int row = it >> 2, seg = it & 3;
        cp_async16(dst + row * ROWB + seg * 16, g + (size_t)row * ldg + seg * 8);
    }
}

template<bool SPLIT>
__device__ __forceinline__ void gemm_body(
    uint32_t sbase, int bn, int bm, int b,
    const f16* __restrict__ Ah, const f16* __restrict__ Al,
    const f16* __restrict__ Bh, const f16* __restrict__ Bl,
    float* __restrict__ C, int K,
    size_t strideA, size_t strideB, size_t strideC, int lda, int ldb, int ldc)
{
    const uint32_t STG = (SPLIT ? 4 : 2) * ARR;

    const f16* Ahp = Ah + (size_t)b * strideA + (size_t)(bm * 128) * lda;
    const f16* Alp = SPLIT ? Al + (size_t)b * strideA + (size_t)(bm * 128) * lda : nullptr;
    const f16* Bhp = Bh + (size_t)b * strideB + (size_t)(bn * 128) * ldb;
    const f16* Blp = SPLIT ? Bl + (size_t)b * strideB + (size_t)(bn * 128) * ldb : nullptr;
    float*     Cb  = C  + (size_t)b * strideC;

    int tid  = threadIdx.x;
    int warp = tid >> 5, lane = tid & 31;
    int wm = warp >> 2, wn = warp & 3;
    int g  = lane >> 2, tg = lane & 3;

    int rA = (lane & 7) + ((lane >> 3) & 1) * 8;
    int cA = (lane >> 4) & 1;
    int rB = (lane & 7) + ((lane >> 4) & 1) * 8;
    int cB = (lane >> 3) & 1;
    uint32_t aOffH = 0 * ARR + (uint32_t)(wm * 64 + rA) * ROWB + cA * 16;
    uint32_t aOffL = 1 * ARR + (uint32_t)(wm * 64 + rA) * ROWB + cA * 16;
    uint32_t bOffH = (SPLIT ? 2 : 1) * ARR + (uint32_t)(wn * 32 + rB) * ROWB + cB * 16;
    uint32_t bOffL = 3 * ARR + (uint32_t)(wn * 32 + rB) * ROWB + cB * 16;

    float acc[4][4][4];
    #pragma unroll
    for (int i = 0; i < 4; i++)
        #pragma unroll
        for (int j = 0; j < 4; j++)
            #pragma unroll
            for (int k = 0; k < 4; k++) acc[i][j][k] = 0.f;

    int NCH = K >> 5;

    load_tile(sbase + 0 * ARR, Ahp, lda, tid);
    if (SPLIT) load_tile(sbase + 1 * ARR, Alp, lda, tid);
    load_tile(sbase + (SPLIT ? 2 : 1) * ARR, Bhp, ldb, tid);
    if (SPLIT) load_tile(sbase + 3 * ARR, Blp, ldb, tid);
    CP_COMMIT();

    for (int c = 0; c < NCH; c++) {
        if (c + 1 < NCH) {
            uint32_t st = sbase + ((c + 1) & 1) * STG;
            int k0 = (c + 1) * 32;
            load_tile(st + 0 * ARR, Ahp + k0, lda, tid);
            if (SPLIT) load_tile(st + 1 * ARR, Alp + k0, lda, tid);
            load_tile(st + (SPLIT ? 2 : 1) * ARR, Bhp + k0, ldb, tid);
            if (SPLIT) load_tile(st + 3 * ARR, Blp + k0, ldb, tid);
            CP_COMMIT();
            CP_WAIT(1);
        } else {
            CP_WAIT(0);
        }
        __syncthreads();

        uint32_t sb = sbase + (c & 1) * STG;
        #pragma unroll
        for (int step = 0; step < 2; step++) {
            unsigned ah[4][4], al[4][4];
            #pragma unroll
            for (int mf = 0; mf < 4; mf++) {
                ldsm4(ah[mf], sb + aOffH + mf * 16 * ROWB + step * 32);
                if (SPLIT) ldsm4(al[mf], sb + aOffL + mf * 16 * ROWB + step * 32);
            }
            unsigned bh[2][4];
            ldsm4(bh[0], sb + bOffH + step * 32);
            ldsm4(bh[1], sb + bOffH + 16 * ROWB + step * 32);
            #pragma unroll
            for (int mf = 0; mf < 4; mf++)
                #pragma unroll
                for (int nf = 0; nf < 4; nf++) {
                    unsigned bfr[2] = { bh[nf >> 1][(nf & 1) * 2],
                                        bh[nf >> 1][(nf & 1) * 2 + 1] };
                    mma_f16(acc[mf][nf], ah[mf], bfr);              // hh
                    if (SPLIT) mma_f16(acc[mf][nf], al[mf], bfr);   // lh
                }
            if (SPLIT) {
                unsigned bl[2][4];
                ldsm4(bl[0], sb + bOffL + step * 32);
                ldsm4(bl[1], sb + bOffL + 16 * ROWB + step * 32);
                #pragma unroll
                for (int mf = 0; mf < 4; mf++)
                    #pragma unroll
                    for (int nf = 0; nf < 4; nf++) {
                        unsigned bfr[2] = { bl[nf >> 1][(nf & 1) * 2],
                                            bl[nf >> 1][(nf & 1) * 2 + 1] };
                        mma_f16(acc[mf][nf], ah[mf], bfr);          // hl
                    }
            }
        }
        __syncthreads();
    }

    #pragma unroll
    for (int mf = 0; mf < 4; mf++) {
        #pragma unroll
        for (int nf = 0; nf < 4; nf++) {
            int r = bm * 128 + wm * 64 + mf * 16 + g;
            int c = bn * 128 + wn * 32 + nf * 8 + tg * 2;
            *(float2*)(Cb + (size_t)r * ldc + c)       = make_float2(acc[mf][nf][0], acc[mf][nf][1]);
            *(float2*)(Cb + (size_t)(r + 8) * ldc + c) = make_float2(acc[mf][nf][2], acc[mf][nf][3]);
        }
    }
}

// ---------------------------------------------------------------------------
// Role bodies: prep (dec split), trans (enc split + transpose), softmax
// ---------------------------------------------------------------------------
__device__ __forceinline__ void prep_body(const float* __restrict__ out_d,
                                          long idx, int b0) {
    long i = idx * 256 + threadIdx.x;          // [0, NB*2048*64)
    int h4 = (int)(i & 63);
    int t  = (int)((i >> 6) & (S_TGT - 1));
    int b  = b0 + (int)(i >> 17);
    float4 v = *(const float4*)(out_d + ((size_t)t * BATCH + b) * HDIM + h4 * 4);
    f16 h[4], l[4];
    split_f16(v.x, h[0], l[0]); split_f16(v.y, h[1], l[1]);
    split_f16(v.z, h[2], l[2]); split_f16(v.w, h[3], l[3]);
    size_t o = ((size_t)b * S_TGT + t) * HDIM + h4 * 4;
    *(uint2*)(g_dec_hi + o) = *(uint2*)h;
    *(uint2*)(g_dec_lo + o) = *(uint2*)l;
}

__device__ __forceinline__ void trans_body(const float* __restrict__ out_e,
                                           uint32_t* tile33, long idx, int b0) {
    // idx -> s0 (64) x h0 (8) x bz (NB)
    int s0 = (int)(idx & 63) * 32;
    int h0 = (int)((idx >> 6) & 7) * 32;
    int b  = b0 + (int)(idx >> 9);
    int x  = threadIdx.x & 31;
    int y0 = threadIdx.x >> 5;
    #pragma unroll
    for (int y = y0; y < 32; y += 8) {
        size_t ebase = ((size_t)(s0 + y) * BATCH + b) * (2 * HDIM) + h0 + x;
        float e = out_e[ebase] + out_e[ebase + HDIM];
        f16 hi, lo;
        split_f16(e, hi, lo);
        tile33[y * 33 + x] = (uint32_t)__half_as_ushort(hi);
        size_t o = ((size_t)b * S_SRC + s0 + y) * HDIM + h0 + x;
        g_enc_hi[o] = hi; g_enc_lo[o] = lo;
    }
    __syncthreads();
    #pragma unroll
    for (int y = y0; y < 32; y += 8) {
        size_t o = ((size_t)b * HDIM + h0 + y) * S_SRC + s0 + x;
        g_encT_hi[o] = __ushort_as_half((unsigned short)tile33[x * 33 + y]);
    }
}

__device__ __forceinline__ void softmax_body(float* red, long idx, int b0) {
    int t = (int)(idx & (S_TGT - 1));
    int b = b0 + (int)(idx >> 11);
    size_t row = (size_t)b * S_TGT + t;
    const float* p = g_S + row * (size_t)S_SRC;
    int tid  = threadIdx.x;
    int lane = tid & 31, warp = tid >> 5;

    float4 v0 = ((const float4*)p)[tid];
    float4 v1 = ((const float4*)p)[tid + 256];

    float m = fmaxf(fmaxf(fmaxf(v0.x, v0.y), fmaxf(v0.z, v0.w)),
                    fmaxf(fmaxf(v1.x, v1.y), fmaxf(v1.z, v1.w)));
    #pragma unroll
    for (int o = 16; o; o >>= 1) m = fmaxf(m, __shfl_xor_sync(0xffffffffu, m, o));
    if (lane == 0) red[warp] = m;
    __syncthreads();
    float bm = red[0];
    #pragma unroll
    for (int i = 1; i < 8; i++) bm = fmaxf(bm, red[i]);
    __syncthreads();

    v0.x = __expf(v0.x - bm); v0.y = __expf(v0.y - bm);
    v0.z = __expf(v0.z - bm); v0.w = __expf(v0.w - bm);
    v1.x = __expf(v1.x - bm); v1.y = __expf(v1.y - bm);
    v1.z = __expf(v1.z - bm); v1.w = __expf(v1.w - bm);

    float s = v0.x + v0.y + v0.z + v0.w + v1.x + v1.y + v1.z + v1.w;
    #pragma unroll
    for (int o = 16; o; o >>= 1) s += __shfl_xor_sync(0xffffffffu, s, o);
    if (lane == 0) red[warp] = s;
    __syncthreads();
    float total = red[0];
    #pragma unroll
    for (int i = 1; i < 8; i++) total += red[i];
    float inv = 1.0f / total;

    f16* ph = g_P_hi + row * (size_t)S_SRC;
    f16 hb0[4] = { __float2half_rn(v0.x * inv), __float2half_rn(v0.y * inv),
                   __float2half_rn(v0.z * inv), __float2half_rn(v0.w * inv) };
    f16 hb1[4] = { __float2half_rn(v1.x * inv), __float2half_rn(v1.y * inv),
                   __float2half_rn(v1.z * inv), __float2half_rn(v1.w * inv) };
    *(uint2*)(ph + (size_t)tid * 4)         = *(uint2*)hb0;
    *(uint2*)(ph + (size_t)(256 + tid) * 4) = *(uint2*)hb1;
}

// ---------------------------------------------------------------------------
// Stage kernel: role-dispatched mega-kernel. Each chunk arg is a chunk id or
// -1 (role absent). Blocks dealt proportionally across roles so tensor-bound
// and DRAM-bound blocks are co-resident on each SM.
// Role block counts per chunk: QK 1024, SM 8192, PV 128, PREP 2048, TRANS 2048
// ---------------------------------------------------------------------------
#define N_QK   1024
#define N_SM   8192
#define N_PV   128
#define N_PREP 2048
#define N_TRANS 2048

__global__ void __launch_bounds__(256, 2) stage_kernel(
    const float* __restrict__ out_d, const float* __restrict__ out_e,
    float* __restrict__ out,
    int cQK, int cSM, int cPV, int cPrep, int cTrans)
{
    extern __shared__ char smem[];
    __shared__ uint32_t tile33[32 * 33];
    __shared__ float red[8];

    int ns[5] = { cQK  >= 0 ? N_QK   : 0,
                  cSM  >= 0 ? N_SM   : 0,
                  cPV  >= 0 ? N_PV   : 0,
                  cPrep>= 0 ? N_PREP : 0,
                  cTrans>=0 ? N_TRANS: 0 };
    long total = (long)ns[0] + ns[1] + ns[2] + ns[3] + ns[4];

    // proportional dealing (Bresenham): role + within-role index
    long i = blockIdx.x, t = total;
    int role = -1; long idx = 0;
    #pragma unroll
    for (int r = 0; r < 5; r++) {
        if (ns[r] > 0) {
            long c0 = i * ns[r] / t, c1 = (i + 1) * ns[r] / t;
            if (c1 > c0) { role = r; idx = c0; break; }
            i -= c0; t -= ns[r];
        }
    }

    uint32_t sbase = smem_u32(smem);

    if (role == 0) {
        // QK: S = dec . enc (3-term split), 128x128 tile
        int bn = (int)(idx & 15), bm = (int)((idx >> 4) & 15), b = cQK * NB + (int)(idx >> 8);
        gemm_body<true>(sbase, bn, bm, b,
            g_dec_hi, g_dec_lo, g_enc_hi, g_enc_lo, g_S, HDIM,
            (size_t)S_TGT * HDIM, (size_t)S_SRC * HDIM, (size_t)S_TGT * S_SRC,
            HDIM, HDIM, S_SRC);
    } else if (role == 1) {
        softmax_body(red, idx, cSM * NB);
    } else if (role == 2) {
        // PV: out = P . encT (plain fp16), 128x128 tile
        int bn = (int)(idx & 1), bm = (int)((idx >> 1) & 15), b = cPV * NB + (int)(idx >> 5);
        gemm_body<false>(sbase, bn, bm, b,
            g_P_hi, nullptr, g_encT_hi, nullptr, out, S_SRC,
            (size_t)S_TGT * S_SRC, (size_t)HDIM * S_SRC, (size_t)HDIM,
            S_SRC, S_SRC, BATCH * HDIM);
    } else if (role == 3) {
        prep_body(out_d, idx, cPrep * NB);
    } else if (role == 4) {
        trans_body(out_e, tile33, idx, cTrans * NB);
    }
}

// ---------------------------------------------------------------------------
extern "C" void kernel_launch(void* const* d_in, const int* in_sizes, int n_in,
                              void* d_out, int out_size) {
    const float* out_e = (const float*)d_in[0];
    const float* out_d = (const float*)d_in[1];
    float* out = (float*)d_out;

    cudaFuncSetAttribute(stage_kernel, cudaFuncAttributeMaxDynamicSharedMemorySize, GSMEM3);

    // Software pipeline: QK(j) | SM(j-1) | PV(j-2) | prep/trans(j+1)
    const int S[7][5] = {
        // qk, sm, pv, prep, trans
        { -1, -1, -1,  0,  0 },
        {  0, -1, -1,  1,  1 },
        {  1,  0, -1,  2,  2 },
        {  2,  1,  0,  3,  3 },
        {  3,  2,  1, -1, -1 },
        { -1,  3,  2, -1, -1 },
        { -1, -1,  3, -1, -1 },
    };
    for (int s = 0; s < 7; s++) {
        long total = (S[s][0] >= 0 ? N_QK : 0) + (S[s][1] >= 0 ? N_SM : 0) +
                     (S[s][2] >= 0 ? N_PV : 0) + (S[s][3] >= 0 ? N_PREP : 0) +
                     (S[s][4] >= 0 ? N_TRANS : 0);
        stage_kernel<<<(unsigned)total, 256, GSMEM3>>>(
            out_d, out_e, out, S[s][0], S[s][1], S[s][2], S[s][3], S[s][4]);
    }
}

// round 10
// speedup vs baseline: 1.2848x; 1.2848x over previous
#include <cuda_runtime.h>
#include <cuda_fp16.h>
#include <cstdint>
#include <cstddef>

#define S_SRC 2048
#define S_TGT 2048
#define BATCH 16
#define HDIM  256
#define NCHUNK 4
#define NB     (BATCH / NCHUNK)

typedef __half f16;

// ---------------------------------------------------------------------------
// Device-global scratch (allocation-free rule)
// ---------------------------------------------------------------------------
__device__ f16   g_dec_hi [(size_t)BATCH * S_TGT * HDIM];   // [b][t][h]
__device__ f16   g_dec_lo [(size_t)BATCH * S_TGT * HDIM];
__device__ f16   g_enc_hi [(size_t)BATCH * S_SRC * HDIM];   // [b][s][h]
__device__ f16   g_enc_lo [(size_t)BATCH * S_SRC * HDIM];
__device__ f16   g_encT_hi[(size_t)BATCH * HDIM  * S_SRC];  // [b][h][s]
__device__ float g_S      [(size_t)BATCH * S_TGT * S_SRC];  // fp32 scores
__device__ f16   g_P_hi   [(size_t)BATCH * S_TGT * S_SRC];  // probs fp16

__device__ __forceinline__ uint32_t smem_u32(const void* p) {
    uint32_t a;
    asm("{ .reg .u64 t; cvta.to.shared.u64 t, %1; cvt.u32.u64 %0, t; }" : "=r"(a) : "l"(p));
    return a;
}
__device__ __forceinline__ void cp_async16(uint32_t dst, const void* src) {
    asm volatile("cp.async.cg.shared.global [%0], [%1], 16;" :: "r"(dst), "l"(src));
}
#define CP_COMMIT() asm volatile("cp.async.commit_group;")
#define CP_WAIT(N)  asm volatile("cp.async.wait_group %0;" :: "n"(N))

__device__ __forceinline__ void ldsm4(unsigned* r, uint32_t a) {
    asm volatile("ldmatrix.sync.aligned.m8n8.x4.shared.b16 {%0,%1,%2,%3}, [%4];"
                 : "=r"(r[0]), "=r"(r[1]), "=r"(r[2]), "=r"(r[3]) : "r"(a));
}
__device__ __forceinline__ void mma_f16(float* d, const unsigned* a, const unsigned* b) {
    asm volatile(
        "mma.sync.aligned.m16n8k16.row.col.f32.f16.f16.f32 "
        "{%0,%1,%2,%3}, {%4,%5,%6,%7}, {%8,%9}, {%0,%1,%2,%3};\n"
        : "+f"(d[0]), "+f"(d[1]), "+f"(d[2]), "+f"(d[3])
        : "r"(a[0]), "r"(a[1]), "r"(a[2]), "r"(a[3]), "r"(b[0]), "r"(b[1]));
}
// f16-accumulator variant (cross terms only; flushed to f32 per chunk)
__device__ __forceinline__ void mma_f16acc(unsigned* d, const unsigned* a, const unsigned* b) {
    asm volatile(
        "mma.sync.aligned.m16n8k16.row.col.f16.f16.f16.f16 "
        "{%0,%1}, {%2,%3,%4,%5}, {%6,%7}, {%0,%1};\n"
        : "+r"(d[0]), "+r"(d[1])
        : "r"(a[0]), "r"(a[1]), "r"(a[2]), "r"(a[3]), "r"(b[0]), "r"(b[1]));
}
__device__ __forceinline__ void split_f16(float v, f16& hi, f16& lo) {
    hi = __float2half_rn(v);
    lo = __float2half_rn(v - __half2float(hi));
}

// ---------------------------------------------------------------------------
// Kernel 1: dec split fp16, batch-major, vectorized
// ---------------------------------------------------------------------------
__global__ void __launch_bounds__(256) prep_dec(const float* __restrict__ out_d) {
    int i = blockIdx.x * blockDim.x + threadIdx.x;
    int h4 = i & (HDIM / 4 - 1);
    int t  = i >> 6;
    int b  = blockIdx.z;
    float4 v = *(const float4*)(out_d + ((size_t)t * BATCH + b) * HDIM + h4 * 4);
    f16 h[4], l[4];
    split_f16(v.x, h[0], l[0]); split_f16(v.y, h[1], l[1]);
    split_f16(v.z, h[2], l[2]); split_f16(v.w, h[3], l[3]);
    size_t idx = ((size_t)b * S_TGT + t) * HDIM + h4 * 4;
    *(uint2*)(g_dec_hi + idx) = *(uint2*)h;
    *(uint2*)(g_dec_lo + idx) = *(uint2*)l;
}

// ---------------------------------------------------------------------------
// Kernel 2: enc = dir0+dir1 split fp16 (row-major hi/lo + transposed hi)
// ---------------------------------------------------------------------------
__global__ void __launch_bounds__(256) transposeE_kernel(const float* __restrict__ out_e) {
    __shared__ uint32_t tile[32][33];
    int b  = blockIdx.z;
    int s0 = blockIdx.x * 32;
    int h0 = blockIdx.y * 32;
    int x = threadIdx.x;
    #pragma unroll
    for (int y = threadIdx.y; y < 32; y += 8) {
        size_t ebase = ((size_t)(s0 + y) * BATCH + b) * (2 * HDIM) + h0 + x;
        float e = out_e[ebase] + out_e[ebase + HDIM];
        f16 hi, lo;
        split_f16(e, hi, lo);
        tile[y][x] = (uint32_t)__half_as_ushort(hi);
        size_t o = ((size_t)b * S_SRC + s0 + y) * HDIM + h0 + x;
        g_enc_hi[o] = hi; g_enc_lo[o] = lo;
    }
    __syncthreads();
    #pragma unroll
    for (int y = threadIdx.y; y < 32; y += 8) {
        size_t o = ((size_t)b * HDIM + h0 + y) * S_SRC + s0 + x;
        g_encT_hi[o] = __ushort_as_half((unsigned short)tile[x][y]);
    }
}

// ---------------------------------------------------------------------------
// GEMM body. SPLIT (QK): hh in f32-acc, lh+hl in f16-acc flushed per chunk.
// !SPLIT (PV): plain fp16, f32-acc.
// Block 128x128, K-chunk 32, double-buffered cp.async, 8 warps (2m x 4n).
// ---------------------------------------------------------------------------
#define ROWB   80
#define ARR    (128 * ROWB)
#define GSMEM3 (2 * 4 * ARR)   // stage kernel always launches with this

__device__ __forceinline__ void load_tile(uint32_t dst, const f16* __restrict__ g,
                                          int ldg, int tid) {
    #pragma unroll
    for (int it = tid; it < 512; it += 256) {
        int row = it >> 2, seg = it & 3;
        cp_async16(dst + row * ROWB + seg * 16, g + (size_t)row * ldg + seg * 8);
    }
}

template<bool SPLIT>
__device__ __forceinline__ void gemm_body(
    uint32_t sbase, int bn, int bm, int b,
    const f16* __restrict__ Ah, const f16* __restrict__ Al,
    const f16* __restrict__ Bh, const f16* __restrict__ Bl,
    float* __restrict__ C, int K,
    size_t strideA, size_t strideB, size_t strideC, int lda, int ldb, int ldc)
{
    const uint32_t STG = (SPLIT ? 4 : 2) * ARR;

    const f16* Ahp = Ah + (size_t)b * strideA + (size_t)(bm * 128) * lda;
    const f16* Alp = SPLIT ? Al + (size_t)b * strideA + (size_t)(bm * 128) * lda : nullptr;
    const f16* Bhp = Bh + (size_t)b * strideB + (size_t)(bn * 128) * ldb;
    const f16* Blp = SPLIT ? Bl + (size_t)b * strideB + (size_t)(bn * 128) * ldb : nullptr;
    float*     Cb  = C  + (size_t)b * strideC;

    int tid  = threadIdx.x;
    int warp = tid >> 5, lane = tid & 31;
    int wm = warp >> 2, wn = warp & 3;
    int g  = lane >> 2, tg = lane & 3;

    int rA = (lane & 7) + ((lane >> 3) & 1) * 8;
    int cA = (lane >> 4) & 1;
    int rB = (lane & 7) + ((lane >> 4) & 1) * 8;
    int cB = (lane >> 3) & 1;
    uint32_t aOffH = 0 * ARR + (uint32_t)(wm * 64 + rA) * ROWB + cA * 16;
    uint32_t aOffL = 1 * ARR + (uint32_t)(wm * 64 + rA) * ROWB + cA * 16;
    uint32_t bOffH = (SPLIT ? 2 : 1) * ARR + (uint32_t)(wn * 32 + rB) * ROWB + cB * 16;
    uint32_t bOffL = 3 * ARR + (uint32_t)(wn * 32 + rB) * ROWB + cB * 16;

    float acc[4][4][4];
    #pragma unroll
    for (int i = 0; i < 4; i++)
        #pragma unroll
        for (int j = 0; j < 4; j++)
            #pragma unroll
            for (int k = 0; k < 4; k++) acc[i][j][k] = 0.f;

    int NCH = K >> 5;

    load_tile(sbase + 0 * ARR, Ahp, lda, tid);
    if (SPLIT) load_tile(sbase + 1 * ARR, Alp, lda, tid);
    load_tile(sbase + (SPLIT ? 2 : 1) * ARR, Bhp, ldb, tid);
    if (SPLIT) load_tile(sbase + 3 * ARR, Blp, ldb, tid);
    CP_COMMIT();

    for (int c = 0; c < NCH; c++) {
        if (c + 1 < NCH) {
            uint32_t st = sbase + ((c + 1) & 1) * STG;
            int k0 = (c + 1) * 32;
            load_tile(st + 0 * ARR, Ahp + k0, lda, tid);
            if (SPLIT) load_tile(st + 1 * ARR, Alp + k0, lda, tid);
            load_tile(st + (SPLIT ? 2 : 1) * ARR, Bhp + k0, ldb, tid);
            if (SPLIT) load_tile(st + 3 * ARR, Blp + k0, ldb, tid);
            CP_COMMIT();
            CP_WAIT(1);
        } else {
            CP_WAIT(0);
        }
        __syncthreads();

        uint32_t sb = sbase + (c & 1) * STG;
        unsigned acc16[4][4][2];
        if (SPLIT) {
            #pragma unroll
            for (int i = 0; i < 4; i++)
                #pragma unroll
                for (int j = 0; j < 4; j++) { acc16[i][j][0] = 0u; acc16[i][j][1] = 0u; }
        }

        #pragma unroll
        for (int step = 0; step < 2; step++) {
            unsigned ah[4][4];
            #pragma unroll
            for (int mf = 0; mf < 4; mf++)
                ldsm4(ah[mf], sb + aOffH + mf * 16 * ROWB + step * 32);
            unsigned bh[2][4];
            ldsm4(bh[0], sb + bOffH + step * 32);
            ldsm4(bh[1], sb + bOffH + 16 * ROWB + step * 32);
            #pragma unroll
            for (int mf = 0; mf < 4; mf++)
                #pragma unroll
                for (int nf = 0; nf < 4; nf++) {
                    unsigned bfr[2] = { bh[nf >> 1][(nf & 1) * 2],
                                        bh[nf >> 1][(nf & 1) * 2 + 1] };
                    mma_f16(acc[mf][nf], ah[mf], bfr);                  // hh
                }
            if (SPLIT) {
                unsigned bl[2][4];
                ldsm4(bl[0], sb + bOffL + step * 32);
                ldsm4(bl[1], sb + bOffL + 16 * ROWB + step * 32);
                #pragma unroll
                for (int mf = 0; mf < 4; mf++)
                    #pragma unroll
                    for (int nf = 0; nf < 4; nf++) {
                        unsigned bfr[2] = { bl[nf >> 1][(nf & 1) * 2],
                                            bl[nf >> 1][(nf & 1) * 2 + 1] };
                        mma_f16acc(acc16[mf][nf], ah[mf], bfr);         // hl (f16 acc)
                    }
                unsigned al[4][4];
                #pragma unroll
                for (int mf = 0; mf < 4; mf++)
                    ldsm4(al[mf], sb + aOffL + mf * 16 * ROWB + step * 32);
                #pragma unroll
                for (int mf = 0; mf < 4; mf++)
                    #pragma unroll
                    for (int nf = 0; nf < 4; nf++) {
                        unsigned bfr[2] = { bh[nf >> 1][(nf & 1) * 2],
                                            bh[nf >> 1][(nf & 1) * 2 + 1] };
                        mma_f16acc(acc16[mf][nf], al[mf], bfr);         // lh (f16 acc)
                    }
            }
        }
        if (SPLIT) {
            #pragma unroll
            for (int mf = 0; mf < 4; mf++)
                #pragma unroll
                for (int nf = 0; nf < 4; nf++) {
                    float2 lo = __half22float2(*(__half2*)&acc16[mf][nf][0]);
                    float2 hi = __half22float2(*(__half2*)&acc16[mf][nf][1]);
                    acc[mf][nf][0] += lo.x; acc[mf][nf][1] += lo.y;
                    acc[mf][nf][2] += hi.x; acc[mf][nf][3] += hi.y;
                }
        }
        __syncthreads();
    }

    #pragma unroll
    for (int mf = 0; mf < 4; mf++) {
        #pragma unroll
        for (int nf = 0; nf < 4; nf++) {
            int r = bm * 128 + wm * 64 + mf * 16 + g;
            int c = bn * 128 + wn * 32 + nf * 8 + tg * 2;
            *(float2*)(Cb + (size_t)r * ldc + c)       = make_float2(acc[mf][nf][0], acc[mf][nf][1]);
            *(float2*)(Cb + (size_t)(r + 8) * ldc + c) = make_float2(acc[mf][nf][2], acc[mf][nf][3]);
        }
    }
}

// ---------------------------------------------------------------------------
// Softmax role: 4 rows per block, 64 threads/row, 32 f32/thread (MLP=8)
// ---------------------------------------------------------------------------
__device__ __forceinline__ void softmax4_body(long idx, int b0,
                                              float* redm, float* reds) {
    int tid  = threadIdx.x;
    int sub  = tid >> 6;          // row 0..3 within block
    int lt   = tid & 63;          // thread within row group
    int lane = tid & 31;
    int w    = (tid >> 5) & 1;    // warp half within row group
    long rg  = idx * 4 + sub;
    int t = (int)(rg & (S_TGT - 1));
    int b = b0 + (int)(rg >> 11);
    size_t row = (size_t)b * S_TGT + t;
    const float* p = g_S + row * (size_t)S_SRC;

    float4 v[8];
    #pragma unroll
    for (int j = 0; j < 8; j++) v[j] = ((const float4*)p)[lt + j * 64];

    float m = -1e30f;
    #pragma unroll
    for (int j = 0; j < 8; j++)
        m = fmaxf(m, fmaxf(fmaxf(v[j].x, v[j].y), fmaxf(v[j].z, v[j].w)));
    #pragma unroll
    for (int o = 16; o; o >>= 1) m = fmaxf(m, __shfl_xor_sync(0xffffffffu, m, o));
    if (lane == 0) redm[sub * 2 + w] = m;
    __syncthreads();
    m = fmaxf(redm[sub * 2], redm[sub * 2 + 1]);

    float s = 0.f;
    #pragma unroll
    for (int j = 0; j < 8; j++) {
        v[j].x = __expf(v[j].x - m); v[j].y = __expf(v[j].y - m);
        v[j].z = __expf(v[j].z - m); v[j].w = __expf(v[j].w - m);
        s += v[j].x + v[j].y + v[j].z + v[j].w;
    }
    #pragma unroll
    for (int o = 16; o; o >>= 1) s += __shfl_xor_sync(0xffffffffu, s, o);
    if (lane == 0) reds[sub * 2 + w] = s;
    __syncthreads();
    float inv = 1.0f / (reds[sub * 2] + reds[sub * 2 + 1]);

    f16* ph = g_P_hi + row * (size_t)S_SRC;
    #pragma unroll
    for (int j = 0; j < 8; j++) {
        f16 h[4] = { __float2half_rn(v[j].x * inv), __float2half_rn(v[j].y * inv),
                     __float2half_rn(v[j].z * inv), __float2half_rn(v[j].w * inv) };
        *(uint2*)(ph + (size_t)(lt + j * 64) * 4) = *(uint2*)h;
    }
}

// ---------------------------------------------------------------------------
// Stage kernel: QK | SM | PV roles, dealt proportionally across blockIdx
// ---------------------------------------------------------------------------
#define N_QK 1024
#define N_SM 2048
#define N_PV 128

__global__ void __launch_bounds__(256, 2) stage_kernel(
    float* __restrict__ out, int cQK, int cSM, int cPV)
{
    extern __shared__ char smem[];
    __shared__ float redm[8], reds[8];

    int ns[3] = { cQK >= 0 ? N_QK : 0,
                  cSM >= 0 ? N_SM : 0,
                  cPV >= 0 ? N_PV : 0 };
    long total = (long)ns[0] + ns[1] + ns[2];

    long i = blockIdx.x, t = total;
    int role = -1; long idx = 0;
    #pragma unroll
    for (int r = 0; r < 3; r++) {
        if (ns[r] > 0) {
            long c0 = i * ns[r] / t, c1 = (i + 1) * ns[r] / t;
            if (c1 > c0) { role = r; idx = c0; break; }
            i -= c0; t -= ns[r];
        }
    }

    uint32_t sbase = smem_u32(smem);

    if (role == 0) {
        int bn = (int)(idx & 15), bm = (int)((idx >> 4) & 15), b = cQK * NB + (int)(idx >> 8);
        gemm_body<true>(sbase, bn, bm, b,
            g_dec_hi, g_dec_lo, g_enc_hi, g_enc_lo, g_S, HDIM,
            (size_t)S_TGT * HDIM, (size_t)S_SRC * HDIM, (size_t)S_TGT * S_SRC,
            HDIM, HDIM, S_SRC);
    } else if (role == 1) {
        softmax4_body(idx, cSM * NB, redm, reds);
    } else if (role == 2) {
        int bn = (int)(idx & 1), bm = (int)((idx >> 1) & 15), b = cPV * NB + (int)(idx >> 5);
        gemm_body<false>(sbase, bn, bm, b,
            g_P_hi, nullptr, g_encT_hi, nullptr, out, S_SRC,
            (size_t)S_TGT * S_SRC, (size_t)HDIM * S_SRC, (size_t)HDIM,
            S_SRC, S_SRC, BATCH * HDIM);
    }
}

// ---------------------------------------------------------------------------
extern "C" void kernel_launch(void* const* d_in, const int* in_sizes, int n_in,
                              void* d_out, int out_size) {
    const float* out_e = (const float*)d_in[0];
    const float* out_d = (const float*)d_in[1];
    float* out = (float*)d_out;

    cudaFuncSetAttribute(stage_kernel, cudaFuncAttributeMaxDynamicSharedMemorySize, GSMEM3);

    // full-occupancy standalone preprocessing
    prep_dec<<<dim3(S_TGT * HDIM / 4 / 256, 1, BATCH), 256>>>(out_d);
    transposeE_kernel<<<dim3(S_SRC / 32, HDIM / 32, BATCH), dim3(32, 8)>>>(out_e);

    // software pipeline: QK(j) | SM(j-1) | PV(j-2)
    const int S[6][3] = {
        {  0, -1, -1 },
        {  1,  0, -1 },
        {  2,  1,  0 },
        {  3,  2,  1 },
        { -1,  3,  2 },
        { -1, -1,  3 },
    };
    for (int s = 0; s < 6; s++) {
        long total = (S[s][0] >= 0 ? N_QK : 0) + (S[s][1] >= 0 ? N_SM : 0) +
                     (S[s][2] >= 0 ? N_PV : 0);
        stage_kernel<<<(unsigned)total, 256, GSMEM3>>>(out, S[s][0], S[s][1], S[s][2]);
    }
}

// round 11
// speedup vs baseline: 1.7687x; 1.3766x over previous
#include <cuda_runtime.h>
#include <cuda_fp16.h>
#include <cstdint>
#include <cstddef>

#define S_SRC 2048
#define S_TGT 2048
#define BATCH 16
#define HDIM  256

typedef __half f16;

// ---------------------------------------------------------------------------
// Device-global scratch (allocation-free rule)
// ---------------------------------------------------------------------------
__device__ f16   g_dec_hi [(size_t)BATCH * S_TGT * HDIM];   // [b][t][h]
__device__ f16   g_dec_lo [(size_t)BATCH * S_TGT * HDIM];
__device__ f16   g_enc_hi [(size_t)BATCH * S_SRC * HDIM];   // [b][s][h]
__device__ f16   g_enc_lo [(size_t)BATCH * S_SRC * HDIM];
__device__ f16   g_encT_hi[(size_t)BATCH * HDIM  * S_SRC];  // [b][h][s]
__device__ float g_S      [(size_t)BATCH * S_TGT * S_SRC];  // fp32 scores
__device__ f16   g_P_hi   [(size_t)BATCH * S_TGT * S_SRC];  // probs fp16

__device__ __forceinline__ uint32_t smem_u32(const void* p) {
    uint32_t a;
    asm("{ .reg .u64 t; cvta.to.shared.u64 t, %1; cvt.u32.u64 %0, t; }" : "=r"(a) : "l"(p));
    return a;
}
__device__ __forceinline__ void cp_async16(uint32_t dst, const void* src) {
    asm volatile("cp.async.cg.shared.global [%0], [%1], 16;" :: "r"(dst), "l"(src));
}
#define CP_COMMIT() asm volatile("cp.async.commit_group;")
#define CP_WAIT(N)  asm volatile("cp.async.wait_group %0;" :: "n"(N))

__device__ __forceinline__ void ldsm4(unsigned* r, uint32_t a) {
    asm volatile("ldmatrix.sync.aligned.m8n8.x4.shared.b16 {%0,%1,%2,%3}, [%4];"
                 : "=r"(r[0]), "=r"(r[1]), "=r"(r[2]), "=r"(r[3]) : "r"(a));
}
__device__ __forceinline__ void mma_f16(float* d, const unsigned* a, const unsigned* b) {
    asm volatile(
        "mma.sync.aligned.m16n8k16.row.col.f32.f16.f16.f32 "
        "{%0,%1,%2,%3}, {%4,%5,%6,%7}, {%8,%9}, {%0,%1,%2,%3};\n"
        : "+f"(d[0]), "+f"(d[1]), "+f"(d[2]), "+f"(d[3])
        : "r"(a[0]), "r"(a[1]), "r"(a[2]), "r"(a[3]), "r"(b[0]), "r"(b[1]));
}
__device__ __forceinline__ void split_f16(float v, f16& hi, f16& lo) {
    hi = __float2half_rn(v);
    lo = __float2half_rn(v - __half2float(hi));
}

// ---------------------------------------------------------------------------
// Kernel 1: dec split fp16, batch-major, vectorized (4 h per thread)
// ---------------------------------------------------------------------------
__global__ void __launch_bounds__(256) prep_dec(const float* __restrict__ out_d) {
    int i = blockIdx.x * blockDim.x + threadIdx.x;
    int h4 = i & (HDIM / 4 - 1);
    int t  = (i >> 6) & (S_TGT - 1);
    int b  = i >> 17;
    float4 v = *(const float4*)(out_d + ((size_t)t * BATCH + b) * HDIM + h4 * 4);
    f16 h[4], l[4];
    split_f16(v.x, h[0], l[0]); split_f16(v.y, h[1], l[1]);
    split_f16(v.z, h[2], l[2]); split_f16(v.w, h[3], l[3]);
    size_t idx = ((size_t)b * S_TGT + t) * HDIM + h4 * 4;
    *(uint2*)(g_dec_hi + idx) = *(uint2*)h;
    *(uint2*)(g_dec_lo + idx) = *(uint2*)l;
}

// ---------------------------------------------------------------------------
// Kernel 2: enc = dir0+dir1 split fp16 (row-major hi/lo + transposed hi)
// ---------------------------------------------------------------------------
__global__ void __launch_bounds__(256) transposeE_kernel(const float* __restrict__ out_e) {
    __shared__ uint32_t tile[32][33];
    int b  = blockIdx.z;
    int s0 = blockIdx.x * 32;
    int h0 = blockIdx.y * 32;
    int x = threadIdx.x;
    #pragma unroll
    for (int y = threadIdx.y; y < 32; y += 8) {
        size_t ebase = ((size_t)(s0 + y) * BATCH + b) * (2 * HDIM) + h0 + x;
        float e = out_e[ebase] + out_e[ebase + HDIM];
        f16 hi, lo;
        split_f16(e, hi, lo);
        tile[y][x] = (uint32_t)__half_as_ushort(hi);
        size_t o = ((size_t)b * S_SRC + s0 + y) * HDIM + h0 + x;
        g_enc_hi[o] = hi; g_enc_lo[o] = lo;
    }
    __syncthreads();
    #pragma unroll
    for (int y = threadIdx.y; y < 32; y += 8) {
        size_t o = ((size_t)b * HDIM + h0 + y) * S_SRC + s0 + x;
        g_encT_hi[o] = __ushort_as_half((unsigned short)tile[x][y]);
    }
}

// ---------------------------------------------------------------------------
// fp16 GEMM:  C[m][n] = sum_k A[m][k]*B[n][k]
// SPLIT: hh + lh + hl, register-sequenced so peak live regs ~104:
//   bh -> ah -> hh | al -> lh | bl (overwrites bh) -> hl
// !SPLIT: plain fp16 single product.
// Block 128x128, K-chunk 32, double-buffered cp.async, 8 warps (2m x 4n),
// __launch_bounds__(256,2): 2 CTAs/SM = 16 warps/SM, no spills.
// ---------------------------------------------------------------------------
#define ROWB   80
#define ARR    (128 * ROWB)

__device__ __forceinline__ void load_tile(uint32_t dst, const f16* __restrict__ g, int ldg) {
    #pragma unroll
    for (int it = threadIdx.x; it < 512; it += 256) {
        int row = it >> 2, seg = it & 3;
        cp_async16(dst + row * ROWB + seg * 16, g + (size_t)row * ldg + seg * 8);
    }
}

template<bool SPLIT>
__global__ void __launch_bounds__(256, 2) gemm_f16(
    const f16* __restrict__ Ah, const f16* __restrict__ Al,
    const f16* __restrict__ Bh, const f16* __restrict__ Bl,
    float* __restrict__ C, int K,
    size_t strideA, size_t strideB, size_t strideC, int lda, int ldb, int ldc)
{
    extern __shared__ char smem[];
    uint32_t sbase = smem_u32(smem);
    const int NARR = SPLIT ? 4 : 2;
    const uint32_t STG = NARR * ARR;

    int b  = blockIdx.z;
    int bm = blockIdx.y, bn = blockIdx.x;
    const f16* Ahp = Ah + (size_t)b * strideA + (size_t)(bm * 128) * lda;
    const f16* Alp = SPLIT ? Al + (size_t)b * strideA + (size_t)(bm * 128) * lda : nullptr;
    const f16* Bhp = Bh + (size_t)b * strideB + (size_t)(bn * 128) * ldb;
    const f16* Blp = SPLIT ? Bl + (size_t)b * strideB + (size_t)(bn * 128) * ldb : nullptr;
    float*     Cb  = C  + (size_t)b * strideC;

    int tid  = threadIdx.x;
    int warp = tid >> 5, lane = tid & 31;
    int wm = warp >> 2, wn = warp & 3;
    int g  = lane >> 2, tg = lane & 3;

    int rA = (lane & 7) + ((lane >> 3) & 1) * 8;
    int cA = (lane >> 4) & 1;
    int rB = (lane & 7) + ((lane >> 4) & 1) * 8;
    int cB = (lane >> 3) & 1;
    uint32_t aOffH = 0 * ARR + (uint32_t)(wm * 64 + rA) * ROWB + cA * 16;
    uint32_t aOffL = 1 * ARR + (uint32_t)(wm * 64 + rA) * ROWB + cA * 16;
    uint32_t bOffH = (SPLIT ? 2 : 1) * ARR + (uint32_t)(wn * 32 + rB) * ROWB + cB * 16;
    uint32_t bOffL = 3 * ARR + (uint32_t)(wn * 32 + rB) * ROWB + cB * 16;

    float acc[4][4][4];
    #pragma unroll
    for (int i = 0; i < 4; i++)
        #pragma unroll
        for (int j = 0; j < 4; j++)
            #pragma unroll
            for (int k = 0; k < 4; k++) acc[i][j][k] = 0.f;

    int NCH = K >> 5;

    load_tile(sbase + 0 * ARR, Ahp, lda);
    if (SPLIT) load_tile(sbase + 1 * ARR, Alp, lda);
    load_tile(sbase + (SPLIT ? 2 : 1) * ARR, Bhp, ldb);
    if (SPLIT) load_tile(sbase + 3 * ARR, Blp, ldb);
    CP_COMMIT();

    for (int c = 0; c < NCH; c++) {
        if (c + 1 < NCH) {
            uint32_t st = sbase + ((c + 1) & 1) * STG;
            int k0 = (c + 1) * 32;
            load_tile(st + 0 * ARR, Ahp + k0, lda);
            if (SPLIT) load_tile(st + 1 * ARR, Alp + k0, lda);
            load_tile(st + (SPLIT ? 2 : 1) * ARR, Bhp + k0, ldb);
            if (SPLIT) load_tile(st + 3 * ARR, Blp + k0, ldb);
            CP_COMMIT();
            CP_WAIT(1);
        } else {
            CP_WAIT(0);
        }
        __syncthreads();

        uint32_t sb = sbase + (c & 1) * STG;
        #pragma unroll
        for (int step = 0; step < 2; step++) {
            // B fragments (bh first, later overwritten by bl)
            unsigned bfr[2][4];
            ldsm4(bfr[0], sb + bOffH + step * 32);
            ldsm4(bfr[1], sb + bOffH + 16 * ROWB + step * 32);
            // A hi fragments
            unsigned ah[4][4];
            #pragma unroll
            for (int mf = 0; mf < 4; mf++)
                ldsm4(ah[mf], sb + aOffH + mf * 16 * ROWB + step * 32);
            // hh
            #pragma unroll
            for (int mf = 0; mf < 4; mf++)
                #pragma unroll
                for (int nf = 0; nf < 4; nf++) {
                    unsigned bb[2] = { bfr[nf >> 1][(nf & 1) * 2],
                                       bfr[nf >> 1][(nf & 1) * 2 + 1] };
                    mma_f16(acc[mf][nf], ah[mf], bb);
                }
            if (SPLIT) {
                // A lo fragments, lh = al x bh
                unsigned al[4][4];
                #pragma unroll
                for (int mf = 0; mf < 4; mf++)
                    ldsm4(al[mf], sb + aOffL + mf * 16 * ROWB + step * 32);
                #pragma unroll
                for (int mf = 0; mf < 4; mf++)
                    #pragma unroll
                    for (int nf = 0; nf < 4; nf++) {
                        unsigned bb[2] = { bfr[nf >> 1][(nf & 1) * 2],
                                           bfr[nf >> 1][(nf & 1) * 2 + 1] };
                        mma_f16(acc[mf][nf], al[mf], bb);
                    }
                // bl overwrites bh, hl = ah x bl
                ldsm4(bfr[0], sb + bOffL + step * 32);
                ldsm4(bfr[1], sb + bOffL + 16 * ROWB + step * 32);
                #pragma unroll
                for (int mf = 0; mf < 4; mf++)
                    #pragma unroll
                    for (int nf = 0; nf < 4; nf++) {
                        unsigned bb[2] = { bfr[nf >> 1][(nf & 1) * 2],
                                           bfr[nf >> 1][(nf & 1) * 2 + 1] };
                        mma_f16(acc[mf][nf], ah[mf], bb);
                    }
            }
        }
        __syncthreads();
    }

    #pragma unroll
    for (int mf = 0; mf < 4; mf++) {
        #pragma unroll
        for (int nf = 0; nf < 4; nf++) {
            int r = bm * 128 + wm * 64 + mf * 16 + g;
            int c = bn * 128 + wn * 32 + nf * 8 + tg * 2;
            *(float2*)(Cb + (size_t)r * ldc + c)       = make_float2(acc[mf][nf][0], acc[mf][nf][1]);
            *(float2*)(Cb + (size_t)(r + 8) * ldc + c) = make_float2(acc[mf][nf][2], acc[mf][nf][3]);
        }
    }
}

#define GSMEM3 (2 * 4 * ARR)
#define GSMEM1 (2 * 2 * ARR)

// ---------------------------------------------------------------------------
// Kernel 4: softmax over s, reads fp32 S, writes fp16 P
// ---------------------------------------------------------------------------
__global__ void __launch_bounds__(256) softmax_kernel() {
    __shared__ float red[8];
    size_t row = blockIdx.x;
    const float* p = g_S + row * (size_t)S_SRC;
    int tid  = threadIdx.x;
    int lane = tid & 31, warp = tid >> 5;

    float4 v0 = ((const float4*)p)[tid];
    float4 v1 = ((const float4*)p)[tid + 256];

    float m = fmaxf(fmaxf(fmaxf(v0.x, v0.y), fmaxf(v0.z, v0.w)),
                    fmaxf(fmaxf(v1.x, v1.y), fmaxf(v1.z, v1.w)));
    #pragma unroll
    for (int o = 16; o; o >>= 1) m = fmaxf(m, __shfl_xor_sync(0xffffffffu, m, o));
    if (lane == 0) red[warp] = m;
    __syncthreads();
    float bm = red[0];
    #pragma unroll
    for (int i = 1; i < 8; i++) bm = fmaxf(bm, red[i]);
    __syncthreads();

    v0.x = __expf(v0.x - bm); v0.y = __expf(v0.y - bm);
    v0.z = __expf(v0.z - bm); v0.w = __expf(v0.w - bm);
    v1.x = __expf(v1.x - bm); v1.y = __expf(v1.y - bm);
    v1.z = __expf(v1.z - bm); v1.w = __expf(v1.w - bm);

    float s = v0.x + v0.y + v0.z + v0.w + v1.x + v1.y + v1.z + v1.w;
    #pragma unroll
    for (int o = 16; o; o >>= 1) s += __shfl_xor_sync(0xffffffffu, s, o);
    if (lane == 0) red[warp] = s;
    __syncthreads();
    float total = red[0];
    #pragma unroll
    for (int i = 1; i < 8; i++) total += red[i];
    float inv = 1.0f / total;

    f16* ph = g_P_hi + row * (size_t)S_SRC;
    f16 hb0[4] = { __float2half_rn(v0.x * inv), __float2half_rn(v0.y * inv),
                   __float2half_rn(v0.z * inv), __float2half_rn(v0.w * inv) };
    f16 hb1[4] = { __float2half_rn(v1.x * inv), __float2half_rn(v1.y * inv),
                   __float2half_rn(v1.z * inv), __float2half_rn(v1.w * inv) };
    *(uint2*)(ph + (size_t)tid * 4)         = *(uint2*)hb0;
    *(uint2*)(ph + (size_t)(256 + tid) * 4) = *(uint2*)hb1;
}

// ---------------------------------------------------------------------------
extern "C" void kernel_launch(void* const* d_in, const int* in_sizes, int n_in,
                              void* d_out, int out_size) {
    const float* out_e = (const float*)d_in[0];
    const float* out_d = (const float*)d_in[1];
    float* out = (float*)d_out;

    f16 *pDh, *pDl, *pEh, *pEl, *pTh, *pPh;
    float* pS;
    cudaGetSymbolAddress((void**)&pDh, g_dec_hi);
    cudaGetSymbolAddress((void**)&pDl, g_dec_lo);
    cudaGetSymbolAddress((void**)&pEh, g_enc_hi);
    cudaGetSymbolAddress((void**)&pEl, g_enc_lo);
    cudaGetSymbolAddress((void**)&pTh, g_encT_hi);
    cudaGetSymbolAddress((void**)&pPh, g_P_hi);
    cudaGetSymbolAddress((void**)&pS,  g_S);

    cudaFuncSetAttribute(gemm_f16<true>,  cudaFuncAttributeMaxDynamicSharedMemorySize, GSMEM3);
    cudaFuncSetAttribute(gemm_f16<false>, cudaFuncAttributeMaxDynamicSharedMemorySize, GSMEM1);

    prep_dec<<<(BATCH * S_TGT * HDIM / 4) / 256, 256>>>(out_d);

    transposeE_kernel<<<dim3(S_SRC / 32, HDIM / 32, BATCH), dim3(32, 8)>>>(out_e);

    // QK: S[b][t][s] = dec . enc  (M=2048, N=2048, K=256), 3-term split fp16
    gemm_f16<true><<<dim3(S_SRC / 128, S_TGT / 128, BATCH), 256, GSMEM3>>>(
        pDh, pDl, pEh, pEl, pS, HDIM,
        (size_t)S_TGT * HDIM, (size_t)S_SRC * HDIM, (size_t)S_TGT * S_SRC,
        HDIM, HDIM, S_SRC);

    softmax_kernel<<<BATCH * S_TGT, 256>>>();

    // PV: out[t][b][h] = P . encT  (M=2048, N=256, K=2048), plain fp16
    gemm_f16<false><<<dim3(HDIM / 128, S_TGT / 128, BATCH), 256, GSMEM1>>>(
        pPh, nullptr, pTh, nullptr, out, S_SRC,
        (size_t)S_TGT * S_SRC, (size_t)HDIM * S_SRC, (size_t)HDIM,
        S_SRC, S_SRC, BATCH * HDIM);
}